// round 16
// baseline (speedup 1.0000x reference)
#include <cuda_runtime.h>
#include <cstdint>

// Problem constants: B=1, Z=1, X=Y=360, C=80, Np=1,993,728
#define XDIM  360
#define YDIM  360
#define CDIM  80
#define CELLS (XDIM * YDIM)          // 129600 = 4050 * 32
#define SLOT_SHIFT 6                 // 64 slots/cell; lambda=15.4 -> P(>64)~1e-21

// Per-cell pid buckets, presented to gather as packed-with-stride-64:
// g_offset[cell] = cell<<6 (written by init), g_count = live histogram.
__device__ __align__(256) int g_pid[CELLS << SLOT_SHIFT];   // 33.2 MB
__device__ __align__(256) int g_count[CELLS];
__device__ __align__(256) int g_offset[CELLS];

// ---------------------------------------------------------------------------
// 0) init: zero counters + materialize constant bucket bases. Same values
//    every replay -> deterministic. (Gather stays store-free: R11 lesson.)
// ---------------------------------------------------------------------------
__global__ void init_kernel() {
    int i = blockIdx.x * blockDim.x + threadIdx.x;
    if (i < CELLS) {
        g_count[i]  = 0;
        g_offset[i] = i << SLOT_SHIFT;
    }
}

// ---------------------------------------------------------------------------
// 1) bucket: cell index + direct pid scatter (fused idx+scan+reorder).
// XLA reciprocal-multiply binning (validated: rel_err ~6e-8):
//   lo = BX - DX/2 in f32; idx = floor((v - lo) * f32(1/DX))
// ---------------------------------------------------------------------------
__global__ void bucket_kernel(const float* __restrict__ geom, int np) {
    int p = blockIdx.x * blockDim.x + threadIdx.x;
    if (p >= np) return;

    float gx = geom[3 * (size_t)p + 0];
    float gy = geom[3 * (size_t)p + 1];
    float gz = geom[3 * (size_t)p + 2];

    const float lox = -53.85f - 0.3f * 0.5f;   // -54.0f in f32
    const float loz =   0.0f  - 20.0f * 0.5f;  // -10.0f
    const float rxy = 1.0f / 0.3f;             // rn f32 reciprocal
    const float rz  = 1.0f / 20.0f;            // exact

    int xi = (int)floorf((gx - lox) * rxy);
    int yi = (int)floorf((gy - lox) * rxy);
    int zi = (int)floorf((gz - loz) * rz);

    bool kept = (xi >= 0) & (xi < XDIM) & (yi >= 0) & (yi < YDIM) &
                (zi >= 0) & (zi < 1);
    if (!kept) return;

    int cell = xi * YDIM + yi;                 // B=1, Z=1 -> xi*360+yi
    int pos = atomicAdd(&g_count[cell], 1);
    if (pos < (1 << SLOT_SHIFT))
        g_pid[(cell << SLOT_SHIFT) + pos] = p;
}

// ---------------------------------------------------------------------------
// 2) gather — champion with ONE controlled change: unroll 4 -> 6.
//    Est. ~46 regs, under the lb(1024) 64-reg ceiling (no reg-tip risk).
//    Everything else identical: 1024 threads, loop inside lane<20 guard,
//    g_offset/g_count/g_pid loads, smem-transpose epilogue, no reset store.
// ---------------------------------------------------------------------------
__global__ __launch_bounds__(1024) void gather_kernel(
    const float* __restrict__ feats, float* __restrict__ out)
{
    __shared__ float s[32][81];   // [local cell][channel], stride 81

    int lane = threadIdx.x & 31;
    int wid  = threadIdx.x >> 5;            // local cell 0..31
    int cell = blockIdx.x * 32 + wid;       // CELLS = 4050*32 exact

    int start = g_offset[cell];
    int cnt   = g_count[cell];

    const float4* f4 = reinterpret_cast<const float4*>(feats);

    if (lane < 20) {
        float4 acc = make_float4(0.f, 0.f, 0.f, 0.f);
        int j = 0;
        for (; j + 5 < cnt; j += 6) {
            int p0 = g_pid[start + j];
            int p1 = g_pid[start + j + 1];
            int p2 = g_pid[start + j + 2];
            int p3 = g_pid[start + j + 3];
            int p4 = g_pid[start + j + 4];
            int p5 = g_pid[start + j + 5];
            float4 v0 = f4[(size_t)p0 * 20 + lane];
            float4 v1 = f4[(size_t)p1 * 20 + lane];
            float4 v2 = f4[(size_t)p2 * 20 + lane];
            float4 v3 = f4[(size_t)p3 * 20 + lane];
            float4 v4 = f4[(size_t)p4 * 20 + lane];
            float4 v5 = f4[(size_t)p5 * 20 + lane];
            acc.x += v0.x; acc.y += v0.y; acc.z += v0.z; acc.w += v0.w;
            acc.x += v1.x; acc.y += v1.y; acc.z += v1.z; acc.w += v1.w;
            acc.x += v2.x; acc.y += v2.y; acc.z += v2.z; acc.w += v2.w;
            acc.x += v3.x; acc.y += v3.y; acc.z += v3.z; acc.w += v3.w;
            acc.x += v4.x; acc.y += v4.y; acc.z += v4.z; acc.w += v4.w;
            acc.x += v5.x; acc.y += v5.y; acc.z += v5.z; acc.w += v5.w;
        }
        for (; j < cnt; j++) {
            int p0 = g_pid[start + j];
            float4 v0 = f4[(size_t)p0 * 20 + lane];
            acc.x += v0.x; acc.y += v0.y; acc.z += v0.z; acc.w += v0.w;
        }
        int c = 4 * lane;
        s[wid][c + 0] = acc.x;
        s[wid][c + 1] = acc.y;
        s[wid][c + 2] = acc.z;
        s[wid][c + 3] = acc.w;
    }
    __syncthreads();

    // write out: 80 c x 32 xy = 2560 floats; 32 consecutive xy per channel row
    int xy0 = blockIdx.x * 32;
    #pragma unroll
    for (int r = 0; r < 3; r++) {
        int linear = r * 1024 + threadIdx.x;
        if (linear < CDIM * 32) {
            int c = linear >> 5;          // channel
            int x = linear & 31;          // local xy
            out[(size_t)c * CELLS + xy0 + x] = s[x][c];
        }
    }
}

// ---------------------------------------------------------------------------
// Launch (3 kernels)
// ---------------------------------------------------------------------------
extern "C" void kernel_launch(void* const* d_in, const int* in_sizes, int n_in,
                              void* d_out, int out_size)
{
    const float* geom  = (const float*)d_in[0];
    const float* feats = (const float*)d_in[1];
    float* out = (float*)d_out;

    int np = in_sizes[0] / 3;   // 1,993,728

    init_kernel<<<(CELLS + 255) / 256, 256>>>();
    bucket_kernel<<<(np + 255) / 256, 256>>>(geom, np);
    gather_kernel<<<CELLS / 32, 1024>>>(feats, out);
}